// round 5
// baseline (speedup 1.0000x reference)
#include <cuda_runtime.h>
#include <math.h>

#define BATCH 16
#define C_IN 103
#define C_CONV 256
#define N_OUT 103
#define D_OUT 16
#define REC 8343
#define H1_DIM 5562
#define H2_DIM 12514
#define K1 1648
#define CONV_G 8

typedef unsigned long long u64;

// ---------------- static device workspace ----------------
__device__ float g_p[BATCH * C_CONV];
__device__ float g_WsumJ[N_OUT * C_CONV * D_OUT];    // [j][c][o]
__device__ float g_s[N_OUT * BATCH * D_OUT];         // [j][b*16+o]
__device__ float g_f0T[K1 * BATCH];                  // [k][b]
__device__ float g_h1T[H1_DIM * BATCH];
__device__ float g_h2T[H2_DIM * BATCH];
__device__ float g_part[3600000];
__device__ unsigned g_barcnt = 0;                    // monotonic ticket barrier

__device__ __forceinline__ unsigned smem_u32(const void* p) {
    return (unsigned)__cvta_generic_to_shared(p);
}

// ---------------- helpers ----------------
__device__ __forceinline__ float block_reduce_sum(float v, float* sc) {
    int t = threadIdx.x;
#pragma unroll
    for (int o = 16; o > 0; o >>= 1) v += __shfl_xor_sync(0xffffffffu, v, o);
    if ((t & 31) == 0) sc[t >> 5] = v;
    __syncthreads();
    if (t < 32) {
        float w = (t < 8) ? sc[t] : 0.f;
#pragma unroll
        for (int o = 4; o > 0; o >>= 1) w += __shfl_xor_sync(0xffffffffu, w, o);
        if (t == 0) sc[0] = w;
    }
    __syncthreads();
    float r = sc[0];
    __syncthreads();
    return r;
}

__device__ __forceinline__ float block_reduce_max(float v, float* sc) {
    int t = threadIdx.x;
#pragma unroll
    for (int o = 16; o > 0; o >>= 1) v = fmaxf(v, __shfl_xor_sync(0xffffffffu, v, o));
    if ((t & 31) == 0) sc[t >> 5] = v;
    __syncthreads();
    if (t < 32) {
        float w = (t < 8) ? sc[t] : -1e30f;
#pragma unroll
        for (int o = 4; o > 0; o >>= 1) w = fmaxf(w, __shfl_xor_sync(0xffffffffu, w, o));
        if (t == 0) sc[0] = w;
    }
    __syncthreads();
    float r = sc[0];
    __syncthreads();
    return r;
}

// monotonic-ticket global barrier: no reset, survives graph replays
__device__ __forceinline__ void gbar(unsigned nb) {
    __syncthreads();
    if (threadIdx.x == 0) {
        __threadfence();
        unsigned ticket = atomicAdd(&g_barcnt, 1u);
        unsigned target = (ticket / nb + 1u) * nb;
        while (*(volatile unsigned*)&g_barcnt < target) { __nanosleep(64); }
        __threadfence();
    }
    __syncthreads();
}

// ---------------- conv 3x3 VALID + relu + spatial mean -> p[b][oc] ----------------
__global__ void k_conv_mean(const float* __restrict__ x, const float* __restrict__ w,
                            const float* __restrict__ bias) {
    extern __shared__ float smem[];
    float* sx = smem;
    float* sw = sx + C_IN * 81;
    float* sacc = sw + CONV_G * C_IN * 9;
    int b = blockIdx.y;
    int oc0 = blockIdx.x * CONV_G;
    int t = threadIdx.x;
    for (int i = t; i < C_IN * 81; i += blockDim.x) sx[i] = x[b * C_IN * 81 + i];
    for (int i = t; i < CONV_G * C_IN * 9; i += blockDim.x) sw[i] = w[oc0 * C_IN * 9 + i];
    __syncthreads();
    if (t < CONV_G * 49) {
        int ocl = t / 49, pos = t % 49, oy = pos / 7, ox = pos % 7;
        float acc = bias[oc0 + ocl];
        const float* wp = &sw[ocl * C_IN * 9];
        for (int ic = 0; ic < C_IN; ic++) {
            const float* xp = &sx[ic * 81 + oy * 9 + ox];
            const float* wq = &wp[ic * 9];
#pragma unroll
            for (int ky = 0; ky < 3; ky++)
#pragma unroll
                for (int kx = 0; kx < 3; kx++)
                    acc = fmaf(xp[ky * 9 + kx], wq[ky * 3 + kx], acc);
        }
        sacc[t] = fmaxf(acc, 0.f);
    }
    __syncthreads();
    if (t < CONV_G) {
        float s = 0.f;
#pragma unroll
        for (int i = 0; i < 49; i++) s += sacc[t * 49 + i];
        g_p[b * C_CONV + oc0 + t] = s * (1.f / 49.f);
    }
}

// ---------------- WsumJ[j][c][o] = sum_i W_caps[c][j][o][i] ----------------
__global__ void k_wsum(const float* __restrict__ Wc) {
    int e = blockIdx.x * 256 + threadIdx.x;   // 421888 = C_CONV*N_OUT*16
    const float4* p = (const float4*)(Wc + (size_t)e * 32);
    float s = 0.f;
#pragma unroll
    for (int i = 0; i < 8; i++) {
        float4 v = __ldg(p + i);
        s += (v.x + v.y) + (v.z + v.w);
    }
    int c = e / 1648;
    int r = e - c * 1648;
    int j = r >> 4, o = r & 15;
    g_WsumJ[((j << 8) + c) * 16 + o] = s;
}

// ---------------- single persistent routing kernel (3 iters) + epilogue ----------------
__global__ void k_route(float* __restrict__ dout) {
    __shared__ float shw[C_CONV * 17];
    __shared__ float shq[C_CONV * 17];
    __shared__ float shcq[C_CONV * 17];
    __shared__ float shc[C_CONV];
    __shared__ float shv[256];
    __shared__ float shba[16];
    __shared__ float sc[8];
    int j = blockIdx.x, t = threadIdx.x;

    for (int b = 0; b < BATCH; b++) {
        float v = g_p[b * 256 + t];
        float msq = block_reduce_sum(v * v, sc);
        shq[t * 17 + b] = v * sqrtf(msq) / (1.f + msq);
    }
    const float4* wj = (const float4*)(g_WsumJ + (size_t)j * 4096);
#pragma unroll
    for (int r = 0; r < 4; r++) {
        int i4 = r * 256 + t;
        float4 v = wj[i4];
        int c = i4 >> 2, o = (i4 & 3) * 4;
        shw[c * 17 + o] = v.x; shw[c * 17 + o + 1] = v.y;
        shw[c * 17 + o + 2] = v.z; shw[c * 17 + o + 3] = v.w;
    }
    float bv = 1.f;
    __syncthreads();

    int bb = t >> 4, oo = t & 15;
    for (int it = 0; it < 3; it++) {
        float m = block_reduce_max(bv, sc);
        float e = expf(bv - m);
        float ssum = block_reduce_sum(e, sc);
        shc[t] = e / ssum;
        __syncthreads();
        for (int i = t; i < 4096; i += 256) {
            int c = i >> 4, b = i & 15;
            shcq[c * 17 + b] = shc[c] * shq[c * 17 + b];
        }
        __syncthreads();
        float acc = 0.f;
#pragma unroll 8
        for (int c = 0; c < 256; c++) acc = fmaf(shcq[c * 17 + bb], shw[c * 17 + oo], acc);
        __stcg(&g_s[j * 256 + t], acc);
        gbar(N_OUT);
        float msq = 0.f;
#pragma unroll 4
        for (int jj = 0; jj < N_OUT; jj++) {
            float sv = __ldcg(&g_s[jj * 256 + t]);
            msq = fmaf(sv, sv, msq);
        }
        float vv = acc * sqrtf(msq) / (1.f + msq);
        shv[t] = vv;
        __syncthreads();
        if (it < 2) {
            float g = 0.f;
#pragma unroll
            for (int b2 = 0; b2 < BATCH; b2++) {
                float d = 0.f;
#pragma unroll
                for (int o2 = 0; o2 < 16; o2++) d = fmaf(shw[t * 17 + o2], shv[b2 * 16 + o2], d);
                g = fmaf(shq[t * 17 + b2], d, g);
            }
            bv += g * (1.f / 16.f);
            gbar(N_OUT);
        }
    }
    if (t < 16) {
        float r = 0.f;
#pragma unroll
        for (int o2 = 0; o2 < 16; o2++) { float q = shv[t * 16 + o2]; r = fmaf(q, q, r); }
        float ba = sqrtf(r);
        shba[t] = ba;
        dout[t * N_OUT + j] = ba;
    }
    __syncthreads();
    g_f0T[(j * 16 + oo) * 16 + bb] = shv[t] * shba[bb];
}

// ---------------- skinny GEMM (M=16): cp.async double-buffered weight tiles ----------------
#define FMA8(ACC, A0, A1, A2, A3, WP)                                               \
    asm("fma.rn.f32x2 %0,%1,%2,%0;" : "+l"(ACC[0]) : "l"(A0.x), "l"(WP));           \
    asm("fma.rn.f32x2 %0,%1,%2,%0;" : "+l"(ACC[1]) : "l"(A0.y), "l"(WP));           \
    asm("fma.rn.f32x2 %0,%1,%2,%0;" : "+l"(ACC[2]) : "l"(A1.x), "l"(WP));           \
    asm("fma.rn.f32x2 %0,%1,%2,%0;" : "+l"(ACC[3]) : "l"(A1.y), "l"(WP));           \
    asm("fma.rn.f32x2 %0,%1,%2,%0;" : "+l"(ACC[4]) : "l"(A2.x), "l"(WP));           \
    asm("fma.rn.f32x2 %0,%1,%2,%0;" : "+l"(ACC[5]) : "l"(A2.y), "l"(WP));           \
    asm("fma.rn.f32x2 %0,%1,%2,%0;" : "+l"(ACC[6]) : "l"(A3.x), "l"(WP));           \
    asm("fma.rn.f32x2 %0,%1,%2,%0;" : "+l"(ACC[7]) : "l"(A3.y), "l"(WP));

template <int TK>
__global__ __launch_bounds__(256, 4) void k_fc_part(int insel, const float* __restrict__ W,
                                                    int K, int N, int kchunk) {
    extern __shared__ float smem[];
    float* wb0 = smem;                        // TK*256
    float* wb1 = smem + TK * 256;
    float* ab0 = smem + 2 * TK * 256;         // TK*16
    float* ab1 = ab0 + TK * 16;
    const float* inT = (insel == 0) ? g_f0T : (insel == 1) ? g_h1T : g_h2T;
    int t = threadIdx.x;
    int k0 = blockIdx.y * kchunk;
    int kn = min(K - k0, kchunk);
    int n = blockIdx.x * 256 + t;
    unsigned waddr0 = smem_u32(wb0) + t * 4u;
    unsigned waddr1 = smem_u32(wb1) + t * 4u;
    unsigned aaddr0 = smem_u32(ab0);
    unsigned aaddr1 = smem_u32(ab1);
    const float* Wbase = W + (size_t)k0 * N;

    // prefetch one tile into buffer b
    auto prefetch = [&](int kt, int b) {
        unsigned wa = b ? waddr1 : waddr0;
        unsigned aa = b ? aaddr1 : aaddr0;
#pragma unroll
        for (int k = 0; k < TK; k++) {
            int kk = kt + k;
            int ok = (kk < kn && n < N) ? 4 : 0;
            const float* s = ok ? (Wbase + (size_t)kk * N + n) : W;
            asm volatile("cp.async.ca.shared.global [%0],[%1],4,%2;"
                         :: "r"(wa + (unsigned)(k * 1024)), "l"(s), "r"(ok));
        }
        if (t < 64) {
            int vb = (kn - kt) * 64 - t * 16;
            int sz = vb < 0 ? 0 : (vb > 16 ? 16 : vb);
            const float* s = sz ? (inT + (size_t)(k0 + kt) * 16 + t * 4) : inT;
            asm volatile("cp.async.cg.shared.global [%0],[%1],16,%2;"
                         :: "r"(aa + (unsigned)(t * 16)), "l"(s), "r"(sz));
        }
        asm volatile("cp.async.commit_group;" ::: "memory");
    };

    u64 acc[8];
#pragma unroll
    for (int i = 0; i < 8; i++) acc[i] = 0ull;

    int ntiles = (kn + TK - 1) / TK;
    prefetch(0, 0);
    for (int ti = 0; ti < ntiles; ti++) {
        int b = ti & 1;
        bool more = (ti + 1 < ntiles);
        if (more) {
            prefetch((ti + 1) * TK, 1 - b);
            asm volatile("cp.async.wait_group 1;" ::: "memory");
        } else {
            asm volatile("cp.async.wait_group 0;" ::: "memory");
        }
        __syncthreads();
        const float* sw = b ? wb1 : wb0;
        const float* sa = b ? ab1 : ab0;
        int kc = min(TK, kn - ti * TK);
#pragma unroll 4
        for (int k = 0; k < kc; k++) {
            float wv = sw[k * 256 + t];
            u64 wp_;
            asm("mov.b64 %0,{%1,%1};" : "=l"(wp_) : "f"(wv));
            const ulonglong2* ap = (const ulonglong2*)(sa + k * 16);
            ulonglong2 A0 = ap[0], A1 = ap[1], A2 = ap[2], A3 = ap[3];
            FMA8(acc, A0, A1, A2, A3, wp_)
        }
        __syncthreads();
    }
    if (n < N) {
        ulonglong2* dst = (ulonglong2*)&g_part[((size_t)blockIdx.y * N + n) * 16];
        dst[0] = make_ulonglong2(acc[0], acc[1]);
        dst[1] = make_ulonglong2(acc[2], acc[3]);
        dst[2] = make_ulonglong2(acc[4], acc[5]);
        dst[3] = make_ulonglong2(acc[6], acc[7]);
    }
}

// ---------------- split-K reduce + bias ----------------
__global__ void k_fc_reduce(const float* __restrict__ bias, int outsel, int N, int ks,
                            float* __restrict__ dout) {
    int gid = blockIdx.x * 256 + threadIdx.x;
    if (gid >= N * 16) return;
    int n = gid >> 4, b = gid & 15;
    float s = __ldg(bias + n);
#pragma unroll 4
    for (int j = 0; j < ks; j++) s += g_part[((size_t)j * N + n) * 16 + b];
    if (outsel == 3) dout[1648 + b * REC + n] = s;
    else if (outsel == 1) g_h1T[gid] = s;
    else g_h2T[gid] = s;
}

// ---------------- launch ----------------
extern "C" void kernel_launch(void* const* d_in, const int* in_sizes, int n_in,
                              void* d_out, int out_size) {
    const float* x   = (const float*)d_in[0];
    const float* cw  = (const float*)d_in[1];
    const float* cb  = (const float*)d_in[2];
    const float* Wc  = (const float*)d_in[3];
    const float* f1w = (const float*)d_in[4];
    const float* f1b = (const float*)d_in[5];
    const float* f2w = (const float*)d_in[6];
    const float* f2b = (const float*)d_in[7];
    const float* f3w = (const float*)d_in[8];
    const float* f3b = (const float*)d_in[9];
    float* out = (float*)d_out;

    static int attr_set = 0;
    int conv_smem = (C_IN * 81 + CONV_G * C_IN * 9 + CONV_G * 49) * 4;
    if (!attr_set) {
        cudaFuncSetAttribute(k_conv_mean, cudaFuncAttributeMaxDynamicSharedMemorySize, conv_smem);
        attr_set = 1;
    }
    const int TK = 16;
    int fc_smem = (2 * TK * 256 + 2 * TK * 16) * 4;   // 34.8 KB

    k_conv_mean<<<dim3(C_CONV / CONV_G, BATCH), 512, conv_smem>>>(x, cw, cb);
    k_wsum<<<1648, 256>>>(Wc);
    k_route<<<N_OUT, 256>>>(out);
    // fc1: K=1648 N=5562: 22 n-blocks × ks=26 = 572 blocks, chunk 64
    k_fc_part<TK><<<dim3(22, 26), 256, fc_smem>>>(0, f1w, K1, H1_DIM, 64);
    k_fc_reduce<<<348, 256>>>(f1b, 1, H1_DIM, 26, out);
    // fc2: K=5562 N=12514: 49 n-blocks × ks=12 = 588 blocks, chunk 464
    k_fc_part<TK><<<dim3(49, 12), 256, fc_smem>>>(1, f2w, H1_DIM, H2_DIM, 464);
    k_fc_reduce<<<783, 256>>>(f2b, 2, H2_DIM, 12, out);
    // fc3: K=12514 N=8343: 33 n-blocks × ks=17 = 561 blocks, chunk 737
    k_fc_part<TK><<<dim3(33, 17), 256, fc_smem>>>(2, f3w, H2_DIM, REC, 737);
    k_fc_reduce<<<522, 256>>>(f3b, 3, REC, 17, out);
}

// round 7
// speedup vs baseline: 1.1212x; 1.1212x over previous
#include <cuda_runtime.h>
#include <math.h>

#define BATCH 16
#define C_IN 103
#define C_CONV 256
#define N_OUT 103
#define D_OUT 16
#define REC 8343
#define H1_DIM 5562
#define H2_DIM 12514
#define K1 1648
#define CONV_G 8

typedef unsigned long long u64;

// ---------------- static device workspace ----------------
__device__ float g_p[BATCH * C_CONV];
__device__ float g_WsumJ[N_OUT * C_CONV * D_OUT];    // [j][c][o]
__device__ float g_s[N_OUT * BATCH * D_OUT];         // [j][b*16+o]
__device__ float g_f0T[K1 * BATCH];                  // [k][b]
__device__ float g_h1T[H1_DIM * BATCH];
__device__ float g_h2T[H2_DIM * BATCH];
__device__ float g_part[4500000];                    // split-K partials
__device__ unsigned g_barcnt = 0;                    // monotonic ticket barrier

__device__ __forceinline__ unsigned smem_u32(const void* p) {
    return (unsigned)__cvta_generic_to_shared(p);
}

// ---------------- helpers ----------------
__device__ __forceinline__ float block_reduce_sum(float v, float* sc) {
    int t = threadIdx.x;
#pragma unroll
    for (int o = 16; o > 0; o >>= 1) v += __shfl_xor_sync(0xffffffffu, v, o);
    if ((t & 31) == 0) sc[t >> 5] = v;
    __syncthreads();
    if (t < 32) {
        float w = (t < 8) ? sc[t] : 0.f;
#pragma unroll
        for (int o = 4; o > 0; o >>= 1) w += __shfl_xor_sync(0xffffffffu, w, o);
        if (t == 0) sc[0] = w;
    }
    __syncthreads();
    float r = sc[0];
    __syncthreads();
    return r;
}

__device__ __forceinline__ float block_reduce_max(float v, float* sc) {
    int t = threadIdx.x;
#pragma unroll
    for (int o = 16; o > 0; o >>= 1) v = fmaxf(v, __shfl_xor_sync(0xffffffffu, v, o));
    if ((t & 31) == 0) sc[t >> 5] = v;
    __syncthreads();
    if (t < 32) {
        float w = (t < 8) ? sc[t] : -1e30f;
#pragma unroll
        for (int o = 4; o > 0; o >>= 1) w = fmaxf(w, __shfl_xor_sync(0xffffffffu, w, o));
        if (t == 0) sc[0] = w;
    }
    __syncthreads();
    float r = sc[0];
    __syncthreads();
    return r;
}

// monotonic-ticket global barrier: no reset, survives graph replays
__device__ __forceinline__ void gbar(unsigned nb) {
    __syncthreads();
    if (threadIdx.x == 0) {
        __threadfence();
        unsigned ticket = atomicAdd(&g_barcnt, 1u);
        unsigned target = (ticket / nb + 1u) * nb;
        while (*(volatile unsigned*)&g_barcnt < target) { __nanosleep(64); }
        __threadfence();
    }
    __syncthreads();
}

// ---------------- conv 3x3 VALID + relu + spatial mean -> p[b][oc] ----------------
__global__ void k_conv_mean(const float* __restrict__ x, const float* __restrict__ w,
                            const float* __restrict__ bias) {
    extern __shared__ float smem[];
    float* sx = smem;
    float* sw = sx + C_IN * 81;
    float* sacc = sw + CONV_G * C_IN * 9;
    int b = blockIdx.y;
    int oc0 = blockIdx.x * CONV_G;
    int t = threadIdx.x;
    for (int i = t; i < C_IN * 81; i += blockDim.x) sx[i] = x[b * C_IN * 81 + i];
    for (int i = t; i < CONV_G * C_IN * 9; i += blockDim.x) sw[i] = w[oc0 * C_IN * 9 + i];
    __syncthreads();
    if (t < CONV_G * 49) {
        int ocl = t / 49, pos = t % 49, oy = pos / 7, ox = pos % 7;
        float acc = bias[oc0 + ocl];
        const float* wp = &sw[ocl * C_IN * 9];
        for (int ic = 0; ic < C_IN; ic++) {
            const float* xp = &sx[ic * 81 + oy * 9 + ox];
            const float* wq = &wp[ic * 9];
#pragma unroll
            for (int ky = 0; ky < 3; ky++)
#pragma unroll
                for (int kx = 0; kx < 3; kx++)
                    acc = fmaf(xp[ky * 9 + kx], wq[ky * 3 + kx], acc);
        }
        sacc[t] = fmaxf(acc, 0.f);
    }
    __syncthreads();
    if (t < CONV_G) {
        float s = 0.f;
#pragma unroll
        for (int i = 0; i < 49; i++) s += sacc[t * 49 + i];
        g_p[b * C_CONV + oc0 + t] = s * (1.f / 49.f);
    }
}

// ---------------- WsumJ[j][c][o] = sum_i W_caps[c][j][o][i] ----------------
__global__ void k_wsum(const float* __restrict__ Wc) {
    int e = blockIdx.x * 256 + threadIdx.x;   // 421888 = C_CONV*N_OUT*16
    const float4* p = (const float4*)(Wc + (size_t)e * 32);
    float s = 0.f;
#pragma unroll
    for (int i = 0; i < 8; i++) {
        float4 v = __ldg(p + i);
        s += (v.x + v.y) + (v.z + v.w);
    }
    int c = e / 1648;
    int r = e - c * 1648;
    int j = r >> 4, o = r & 15;
    g_WsumJ[((j << 8) + c) * 16 + o] = s;
}

// ---------------- single persistent routing kernel (3 iters) + epilogue ----------------
__global__ void k_route(float* __restrict__ dout) {
    __shared__ float shw[C_CONV * 17];
    __shared__ float shq[C_CONV * 17];
    __shared__ float shcq[C_CONV * 17];
    __shared__ float shc[C_CONV];
    __shared__ float shv[256];
    __shared__ float shba[16];
    __shared__ float sc[8];
    int j = blockIdx.x, t = threadIdx.x;

    for (int b = 0; b < BATCH; b++) {
        float v = g_p[b * 256 + t];
        float msq = block_reduce_sum(v * v, sc);
        shq[t * 17 + b] = v * sqrtf(msq) / (1.f + msq);
    }
    const float4* wj = (const float4*)(g_WsumJ + (size_t)j * 4096);
#pragma unroll
    for (int r = 0; r < 4; r++) {
        int i4 = r * 256 + t;
        float4 v = wj[i4];
        int c = i4 >> 2, o = (i4 & 3) * 4;
        shw[c * 17 + o] = v.x; shw[c * 17 + o + 1] = v.y;
        shw[c * 17 + o + 2] = v.z; shw[c * 17 + o + 3] = v.w;
    }
    float bv = 1.f;
    __syncthreads();

    int bb = t >> 4, oo = t & 15;
    for (int it = 0; it < 3; it++) {
        float m = block_reduce_max(bv, sc);
        float e = expf(bv - m);
        float ssum = block_reduce_sum(e, sc);
        shc[t] = e / ssum;
        __syncthreads();
        for (int i = t; i < 4096; i += 256) {
            int c = i >> 4, b = i & 15;
            shcq[c * 17 + b] = shc[c] * shq[c * 17 + b];
        }
        __syncthreads();
        float acc = 0.f;
#pragma unroll 8
        for (int c = 0; c < 256; c++) acc = fmaf(shcq[c * 17 + bb], shw[c * 17 + oo], acc);
        __stcg(&g_s[j * 256 + t], acc);
        gbar(N_OUT);
        float msq = 0.f;
#pragma unroll 4
        for (int jj = 0; jj < N_OUT; jj++) {
            float sv = __ldcg(&g_s[jj * 256 + t]);
            msq = fmaf(sv, sv, msq);
        }
        float vv = acc * sqrtf(msq) / (1.f + msq);
        shv[t] = vv;
        __syncthreads();
        if (it < 2) {
            float g = 0.f;
#pragma unroll
            for (int b2 = 0; b2 < BATCH; b2++) {
                float d = 0.f;
#pragma unroll
                for (int o2 = 0; o2 < 16; o2++) d = fmaf(shw[t * 17 + o2], shv[b2 * 16 + o2], d);
                g = fmaf(shq[t * 17 + b2], d, g);
            }
            bv += g * (1.f / 16.f);
            gbar(N_OUT);
        }
    }
    if (t < 16) {
        float r = 0.f;
#pragma unroll
        for (int o2 = 0; o2 < 16; o2++) { float q = shv[t * 16 + o2]; r = fmaf(q, q, r); }
        float ba = sqrtf(r);
        shba[t] = ba;
        dout[t * N_OUT + j] = ba;
    }
    __syncthreads();
    g_f0T[(j * 16 + oo) * 16 + bb] = shv[t] * shba[bb];
}

// ---------------- skinny GEMM (M=16): cp.async tiles, NPT=4 via LDS.128 ----------------
#define FMA8(ACC, A0, A1, A2, A3, WP)                                               \
    asm("fma.rn.f32x2 %0,%1,%2,%0;" : "+l"(ACC[0]) : "l"(A0.x), "l"(WP));           \
    asm("fma.rn.f32x2 %0,%1,%2,%0;" : "+l"(ACC[1]) : "l"(A0.y), "l"(WP));           \
    asm("fma.rn.f32x2 %0,%1,%2,%0;" : "+l"(ACC[2]) : "l"(A1.x), "l"(WP));           \
    asm("fma.rn.f32x2 %0,%1,%2,%0;" : "+l"(ACC[3]) : "l"(A1.y), "l"(WP));           \
    asm("fma.rn.f32x2 %0,%1,%2,%0;" : "+l"(ACC[4]) : "l"(A2.x), "l"(WP));           \
    asm("fma.rn.f32x2 %0,%1,%2,%0;" : "+l"(ACC[5]) : "l"(A2.y), "l"(WP));           \
    asm("fma.rn.f32x2 %0,%1,%2,%0;" : "+l"(ACC[6]) : "l"(A3.x), "l"(WP));           \
    asm("fma.rn.f32x2 %0,%1,%2,%0;" : "+l"(ACC[7]) : "l"(A3.y), "l"(WP));

#define TKF 8
#define CBLK 1024

__global__ __launch_bounds__(256, 2) void k_fc_part(int insel, const float* __restrict__ W,
                                                    int K, int N, int kchunk) {
    extern __shared__ float smem[];
    float* wb0 = smem;                          // TKF*CBLK
    float* wb1 = smem + TKF * CBLK;
    float* ab0 = smem + 2 * TKF * CBLK;         // TKF*16
    float* ab1 = ab0 + TKF * 16;
    const float* inT = (insel == 0) ? g_f0T : (insel == 1) ? g_h1T : g_h2T;
    int t = threadIdx.x;
    int k0 = blockIdx.y * kchunk;
    int kn = min(K - k0, kchunk);
    int nblk = blockIdx.x * CBLK;
    unsigned wa0 = smem_u32(wb0), wa1 = smem_u32(wb1);
    unsigned aa0 = smem_u32(ab0), aa1 = smem_u32(ab1);

    // prefetch one tile into buffer b
    auto prefetch = [&](int kt, int b) {
        unsigned wa = b ? wa1 : wa0;
        unsigned aa = b ? aa1 : aa0;
#pragma unroll
        for (int k = 0; k < TKF; k++) {
            int kk = kt + k;
            if (kk < kn) {
                size_t rowg = (size_t)(k0 + kk) * N;
                const float* src = W + rowg + nblk;
                unsigned drow = wa + (unsigned)(k * CBLK * 4);
                if (((rowg + nblk) & 1u) == 0) {
                    // 8B path (always for even N; even rows when N odd)
#pragma unroll
                    for (int h = 0; h < 2; h++) {
                        int c = h * 512 + 2 * t;
                        int rem = (N - (nblk + c)) * 4;
                        int sz = rem < 0 ? 0 : (rem > 8 ? 8 : rem);
                        asm volatile("cp.async.ca.shared.global [%0],[%1],8,%2;"
                                     :: "r"(drow + (unsigned)(c * 4)), "l"(src + c), "r"(sz));
                    }
                } else {
                    // 4B path (odd rows when N odd)
#pragma unroll
                    for (int h = 0; h < 2; h++) {
#pragma unroll
                        for (int q = 0; q < 2; q++) {
                            int c = h * 512 + 2 * t + q;
                            int sz = (nblk + c < N) ? 4 : 0;
                            asm volatile("cp.async.ca.shared.global [%0],[%1],4,%2;"
                                         :: "r"(drow + (unsigned)(c * 4)), "l"(src + c), "r"(sz));
                        }
                    }
                }
            }
        }
        if (t < TKF * 4) {
            int vb = (kn - kt) * 64 - t * 16;
            int sz = vb < 0 ? 0 : (vb > 16 ? 16 : vb);
            const float* s = sz ? (inT + (size_t)(k0 + kt) * 16 + t * 4) : inT;
            asm volatile("cp.async.ca.shared.global [%0],[%1],16,%2;"
                         :: "r"(aa + (unsigned)(t * 16)), "l"(s), "r"(sz));
        }
        asm volatile("cp.async.commit_group;" ::: "memory");
    };

    u64 acc[4][8];
#pragma unroll
    for (int i = 0; i < 4; i++)
#pragma unroll
        for (int b = 0; b < 8; b++) acc[i][b] = 0ull;

    int ntiles = (kn + TKF - 1) / TKF;
    prefetch(0, 0);
    for (int ti = 0; ti < ntiles; ti++) {
        int b = ti & 1;
        bool more = (ti + 1 < ntiles);
        if (more) {
            prefetch((ti + 1) * TKF, 1 - b);
            asm volatile("cp.async.wait_group 1;" ::: "memory");
        } else {
            asm volatile("cp.async.wait_group 0;" ::: "memory");
        }
        __syncthreads();
        const float* sw = b ? wb1 : wb0;
        const float* sa = b ? ab1 : ab0;
        int kc = min(TKF, kn - ti * TKF);
#pragma unroll
        for (int k = 0; k < TKF; k++) {
            if (k < kc) {
                float4 w4 = *(const float4*)(sw + k * CBLK + 4 * t);
                const ulonglong2* ap = (const ulonglong2*)(sa + k * 16);
                ulonglong2 A0 = ap[0], A1 = ap[1], A2 = ap[2], A3 = ap[3];
                u64 wp_;
                asm("mov.b64 %0,{%1,%1};" : "=l"(wp_) : "f"(w4.x));
                FMA8(acc[0], A0, A1, A2, A3, wp_)
                asm("mov.b64 %0,{%1,%1};" : "=l"(wp_) : "f"(w4.y));
                FMA8(acc[1], A0, A1, A2, A3, wp_)
                asm("mov.b64 %0,{%1,%1};" : "=l"(wp_) : "f"(w4.z));
                FMA8(acc[2], A0, A1, A2, A3, wp_)
                asm("mov.b64 %0,{%1,%1};" : "=l"(wp_) : "f"(w4.w));
                FMA8(acc[3], A0, A1, A2, A3, wp_)
            }
        }
        __syncthreads();
    }
#pragma unroll
    for (int i = 0; i < 4; i++) {
        int n = nblk + 4 * t + i;
        if (n < N) {
            ulonglong2* dst = (ulonglong2*)&g_part[((size_t)blockIdx.y * N + n) * 16];
            dst[0] = make_ulonglong2(acc[i][0], acc[i][1]);
            dst[1] = make_ulonglong2(acc[i][2], acc[i][3]);
            dst[2] = make_ulonglong2(acc[i][4], acc[i][5]);
            dst[3] = make_ulonglong2(acc[i][6], acc[i][7]);
        }
    }
}

// ---------------- split-K reduce + bias ----------------
__global__ void k_fc_reduce(const float* __restrict__ bias, int outsel, int N, int ks,
                            float* __restrict__ dout) {
    int gid = blockIdx.x * 256 + threadIdx.x;
    if (gid >= N * 16) return;
    int n = gid >> 4, b = gid & 15;
    float s = __ldg(bias + n);
#pragma unroll 4
    for (int j = 0; j < ks; j++) s += g_part[((size_t)j * N + n) * 16 + b];
    if (outsel == 3) dout[1648 + b * REC + n] = s;
    else if (outsel == 1) g_h1T[gid] = s;
    else g_h2T[gid] = s;
}

// ---------------- launch ----------------
extern "C" void kernel_launch(void* const* d_in, const int* in_sizes, int n_in,
                              void* d_out, int out_size) {
    const float* x   = (const float*)d_in[0];
    const float* cw  = (const float*)d_in[1];
    const float* cb  = (const float*)d_in[2];
    const float* Wc  = (const float*)d_in[3];
    const float* f1w = (const float*)d_in[4];
    const float* f1b = (const float*)d_in[5];
    const float* f2w = (const float*)d_in[6];
    const float* f2b = (const float*)d_in[7];
    const float* f3w = (const float*)d_in[8];
    const float* f3b = (const float*)d_in[9];
    float* out = (float*)d_out;

    int conv_smem = (C_IN * 81 + CONV_G * C_IN * 9 + CONV_G * 49) * 4;
    int fc_smem = (2 * TKF * CBLK + 2 * TKF * 16) * 4;   // 66560 B
    static int attr_set = 0;
    if (!attr_set) {
        cudaFuncSetAttribute(k_conv_mean, cudaFuncAttributeMaxDynamicSharedMemorySize, conv_smem);
        cudaFuncSetAttribute(k_fc_part, cudaFuncAttributeMaxDynamicSharedMemorySize, fc_smem);
        attr_set = 1;
    }

    k_conv_mean<<<dim3(C_CONV / CONV_G, BATCH), 512, conv_smem>>>(x, cw, cb);
    k_wsum<<<1648, 256>>>(Wc);
    k_route<<<N_OUT, 256>>>(out);
    // fc1: K=1648 N=5562: 6 n-blocks × ks=49 = 294 blocks, chunk 34
    k_fc_part<<<dim3(6, 49), 256, fc_smem>>>(0, f1w, K1, H1_DIM, 34);
    k_fc_reduce<<<348, 256>>>(f1b, 1, H1_DIM, 49, out);
    // fc2: K=5562 N=12514: 13 n-blocks × ks=22 = 286 blocks, chunk 253
    k_fc_part<<<dim3(13, 22), 256, fc_smem>>>(1, f2w, H1_DIM, H2_DIM, 253);
    k_fc_reduce<<<783, 256>>>(f2b, 2, H2_DIM, 22, out);
    // fc3: K=12514 N=8343: 9 n-blocks × ks=32 = 288 blocks, chunk 392
    k_fc_part<<<dim3(9, 32), 256, fc_smem>>>(2, f3w, H2_DIM, REC, 392);
    k_fc_reduce<<<522, 256>>>(f3b, 3, REC, 32, out);
}

// round 8
// speedup vs baseline: 1.1424x; 1.0189x over previous
#include <cuda_runtime.h>
#include <math.h>

#define BATCH 16
#define C_IN 103
#define C_CONV 256
#define N_OUT 103
#define D_OUT 16
#define REC 8343
#define H1_DIM 5562
#define H2_DIM 12514
#define K1 1648
#define CONV_G 8

typedef unsigned long long u64;

// ---------------- static device workspace ----------------
__device__ float g_p[BATCH * C_CONV];
__device__ float g_WsumJ[N_OUT * C_CONV * D_OUT];    // [j][c][o]
__device__ float g_s[N_OUT * BATCH * D_OUT];         // [j][b*16+o]
__device__ float g_f0T[K1 * BATCH];                  // [k][b]
__device__ float g_h1T[H1_DIM * BATCH];
__device__ float g_h2T[H2_DIM * BATCH];
__device__ float g_part[4500000];                    // split-K partials
__device__ unsigned g_barcnt = 0;                    // monotonic ticket barrier

__device__ __forceinline__ unsigned smem_u32(const void* p) {
    return (unsigned)__cvta_generic_to_shared(p);
}

// ---------------- helpers ----------------
__device__ __forceinline__ float block_reduce_sum(float v, float* sc) {
    int t = threadIdx.x;
#pragma unroll
    for (int o = 16; o > 0; o >>= 1) v += __shfl_xor_sync(0xffffffffu, v, o);
    if ((t & 31) == 0) sc[t >> 5] = v;
    __syncthreads();
    if (t < 32) {
        float w = (t < 8) ? sc[t] : 0.f;
#pragma unroll
        for (int o = 4; o > 0; o >>= 1) w += __shfl_xor_sync(0xffffffffu, w, o);
        if (t == 0) sc[0] = w;
    }
    __syncthreads();
    float r = sc[0];
    __syncthreads();
    return r;
}

__device__ __forceinline__ float block_reduce_max(float v, float* sc) {
    int t = threadIdx.x;
#pragma unroll
    for (int o = 16; o > 0; o >>= 1) v = fmaxf(v, __shfl_xor_sync(0xffffffffu, v, o));
    if ((t & 31) == 0) sc[t >> 5] = v;
    __syncthreads();
    if (t < 32) {
        float w = (t < 8) ? sc[t] : -1e30f;
#pragma unroll
        for (int o = 4; o > 0; o >>= 1) w = fmaxf(w, __shfl_xor_sync(0xffffffffu, w, o));
        if (t == 0) sc[0] = w;
    }
    __syncthreads();
    float r = sc[0];
    __syncthreads();
    return r;
}

// monotonic-ticket global barrier: no reset, survives graph replays
__device__ __forceinline__ void gbar(unsigned nb) {
    __syncthreads();
    if (threadIdx.x == 0) {
        __threadfence();
        unsigned ticket = atomicAdd(&g_barcnt, 1u);
        unsigned target = (ticket / nb + 1u) * nb;
        while (*(volatile unsigned*)&g_barcnt < target) { __nanosleep(64); }
        __threadfence();
    }
    __syncthreads();
}

// ---------------- conv 3x3 VALID + relu + spatial mean -> p[b][oc] ----------------
__global__ void k_conv_mean(const float* __restrict__ x, const float* __restrict__ w,
                            const float* __restrict__ bias) {
    extern __shared__ float smem[];
    float* sx = smem;
    float* sw = sx + C_IN * 81;
    float* sacc = sw + CONV_G * C_IN * 9;
    int b = blockIdx.y;
    int oc0 = blockIdx.x * CONV_G;
    int t = threadIdx.x;
    for (int i = t; i < C_IN * 81; i += blockDim.x) sx[i] = x[b * C_IN * 81 + i];
    for (int i = t; i < CONV_G * C_IN * 9; i += blockDim.x) sw[i] = w[oc0 * C_IN * 9 + i];
    __syncthreads();
    if (t < CONV_G * 49) {
        int ocl = t / 49, pos = t % 49, oy = pos / 7, ox = pos % 7;
        float acc = bias[oc0 + ocl];
        const float* wp = &sw[ocl * C_IN * 9];
        for (int ic = 0; ic < C_IN; ic++) {
            const float* xp = &sx[ic * 81 + oy * 9 + ox];
            const float* wq = &wp[ic * 9];
#pragma unroll
            for (int ky = 0; ky < 3; ky++)
#pragma unroll
                for (int kx = 0; kx < 3; kx++)
                    acc = fmaf(xp[ky * 9 + kx], wq[ky * 3 + kx], acc);
        }
        sacc[t] = fmaxf(acc, 0.f);
    }
    __syncthreads();
    if (t < CONV_G) {
        float s = 0.f;
#pragma unroll
        for (int i = 0; i < 49; i++) s += sacc[t * 49 + i];
        g_p[b * C_CONV + oc0 + t] = s * (1.f / 49.f);
    }
}

// ---------------- WsumJ[j][c][o] = sum_i W_caps[c][j][o][i] ----------------
__global__ void k_wsum(const float* __restrict__ Wc) {
    int e = blockIdx.x * 256 + threadIdx.x;   // 421888 = C_CONV*N_OUT*16
    const float4* p = (const float4*)(Wc + (size_t)e * 32);
    float s = 0.f;
#pragma unroll
    for (int i = 0; i < 8; i++) {
        float4 v = __ldg(p + i);
        s += (v.x + v.y) + (v.z + v.w);
    }
    int c = e / 1648;
    int r = e - c * 1648;
    int j = r >> 4, o = r & 15;
    g_WsumJ[((j << 8) + c) * 16 + o] = s;
}

// ---------------- single persistent routing kernel (3 iters) + epilogue ----------------
__global__ void k_route(float* __restrict__ dout) {
    __shared__ float shw[C_CONV * 17];
    __shared__ float shq[C_CONV * 17];
    __shared__ float shcq[C_CONV * 17];
    __shared__ float shc[C_CONV];
    __shared__ float shv[256];
    __shared__ float shba[16];
    __shared__ float sc[8];
    int j = blockIdx.x, t = threadIdx.x;

    for (int b = 0; b < BATCH; b++) {
        float v = g_p[b * 256 + t];
        float msq = block_reduce_sum(v * v, sc);
        shq[t * 17 + b] = v * sqrtf(msq) / (1.f + msq);
    }
    const float4* wj = (const float4*)(g_WsumJ + (size_t)j * 4096);
#pragma unroll
    for (int r = 0; r < 4; r++) {
        int i4 = r * 256 + t;
        float4 v = wj[i4];
        int c = i4 >> 2, o = (i4 & 3) * 4;
        shw[c * 17 + o] = v.x; shw[c * 17 + o + 1] = v.y;
        shw[c * 17 + o + 2] = v.z; shw[c * 17 + o + 3] = v.w;
    }
    float bv = 1.f;
    __syncthreads();

    int bb = t >> 4, oo = t & 15;
    for (int it = 0; it < 3; it++) {
        float m = block_reduce_max(bv, sc);
        float e = expf(bv - m);
        float ssum = block_reduce_sum(e, sc);
        shc[t] = e / ssum;
        __syncthreads();
        for (int i = t; i < 4096; i += 256) {
            int c = i >> 4, b = i & 15;
            shcq[c * 17 + b] = shc[c] * shq[c * 17 + b];
        }
        __syncthreads();
        float acc = 0.f;
#pragma unroll 8
        for (int c = 0; c < 256; c++) acc = fmaf(shcq[c * 17 + bb], shw[c * 17 + oo], acc);
        __stcg(&g_s[j * 256 + t], acc);
        gbar(N_OUT);
        float msq = 0.f;
#pragma unroll 4
        for (int jj = 0; jj < N_OUT; jj++) {
            float sv = __ldcg(&g_s[jj * 256 + t]);
            msq = fmaf(sv, sv, msq);
        }
        float vv = acc * sqrtf(msq) / (1.f + msq);
        shv[t] = vv;
        __syncthreads();
        if (it < 2) {
            float g = 0.f;
#pragma unroll
            for (int b2 = 0; b2 < BATCH; b2++) {
                float d = 0.f;
#pragma unroll
                for (int o2 = 0; o2 < 16; o2++) d = fmaf(shw[t * 17 + o2], shv[b2 * 16 + o2], d);
                g = fmaf(shq[t * 17 + b2], d, g);
            }
            bv += g * (1.f / 16.f);
            gbar(N_OUT);
        }
    }
    if (t < 16) {
        float r = 0.f;
#pragma unroll
        for (int o2 = 0; o2 < 16; o2++) { float q = shv[t * 16 + o2]; r = fmaf(q, q, r); }
        float ba = sqrtf(r);
        shba[t] = ba;
        dout[t * N_OUT + j] = ba;
    }
    __syncthreads();
    g_f0T[(j * 16 + oo) * 16 + bb] = shv[t] * shba[bb];
}

// ---------------- skinny GEMM (M=16): 3-stage cp.async pipeline ----------------
#define FMA8(ACC, A0, A1, A2, A3, WP)                                               \
    asm("fma.rn.f32x2 %0,%1,%2,%0;" : "+l"(ACC[0]) : "l"(A0.x), "l"(WP));           \
    asm("fma.rn.f32x2 %0,%1,%2,%0;" : "+l"(ACC[1]) : "l"(A0.y), "l"(WP));           \
    asm("fma.rn.f32x2 %0,%1,%2,%0;" : "+l"(ACC[2]) : "l"(A1.x), "l"(WP));           \
    asm("fma.rn.f32x2 %0,%1,%2,%0;" : "+l"(ACC[3]) : "l"(A1.y), "l"(WP));           \
    asm("fma.rn.f32x2 %0,%1,%2,%0;" : "+l"(ACC[4]) : "l"(A2.x), "l"(WP));           \
    asm("fma.rn.f32x2 %0,%1,%2,%0;" : "+l"(ACC[5]) : "l"(A2.y), "l"(WP));           \
    asm("fma.rn.f32x2 %0,%1,%2,%0;" : "+l"(ACC[6]) : "l"(A3.x), "l"(WP));           \
    asm("fma.rn.f32x2 %0,%1,%2,%0;" : "+l"(ACC[7]) : "l"(A3.y), "l"(WP));

#define TKF 8
#define CBLK 1024
#define WTILE (TKF * CBLK)                  // floats per weight tile
#define ATILE (TKF * 16)

__global__ __launch_bounds__(256, 2) void k_fc_part(int insel, const float* __restrict__ W,
                                                    int K, int N, int kchunk) {
    extern __shared__ float smem[];
    float* wbuf = smem;                      // 3 * WTILE
    float* abuf = smem + 3 * WTILE;          // 3 * ATILE
    const float* inT = (insel == 0) ? g_f0T : (insel == 1) ? g_h1T : g_h2T;
    int t = threadIdx.x;
    int k0 = blockIdx.y * kchunk;
    int kn = min(K - k0, kchunk);
    int nblk = blockIdx.x * CBLK;
    unsigned wbase = smem_u32(wbuf);
    unsigned abase = smem_u32(abuf);
    int ntiles = (kn + TKF - 1) / TKF;

    // prefetch tile kt/TKF into buffer buf; always commits exactly one group
    auto prefetch = [&](int ti, int buf) {
        int kt = ti * TKF;
        if (kt < kn) {
            const float* src = W + (size_t)(k0 + kt) * N + nblk;
            unsigned drow = wbase + (unsigned)(buf * WTILE * 4);
            int kmax = kn - kt;
#pragma unroll
            for (int k = 0; k < TKF; k++) {
                if (k < kmax) {
                    unsigned al = (unsigned)(size_t)src & 15u;
                    if (al == 0u) {
                        int rem = (N - (nblk + 4 * t)) * 4;
                        int sz = rem < 0 ? 0 : (rem > 16 ? 16 : rem);
                        const float* s = sz ? (src + 4 * t) : W;
                        asm volatile("cp.async.cg.shared.global [%0],[%1],16,%2;"
                                     :: "r"(drow + (unsigned)(t * 16)), "l"(s), "r"(sz));
                    } else if (al == 8u) {
#pragma unroll
                        for (int h = 0; h < 2; h++) {
                            int c = h * 512 + 2 * t;
                            int rem = (N - (nblk + c)) * 4;
                            int sz = rem < 0 ? 0 : (rem > 8 ? 8 : rem);
                            const float* s = sz ? (src + c) : W;
                            asm volatile("cp.async.ca.shared.global [%0],[%1],8,%2;"
                                         :: "r"(drow + (unsigned)(c * 4)), "l"(s), "r"(sz));
                        }
                    } else {
#pragma unroll
                        for (int h = 0; h < 4; h++) {
                            int c = h * 256 + t;
                            int sz = (nblk + c < N) ? 4 : 0;
                            const float* s = sz ? (src + c) : W;
                            asm volatile("cp.async.ca.shared.global [%0],[%1],4,%2;"
                                         :: "r"(drow + (unsigned)(c * 4)), "l"(s), "r"(sz));
                        }
                    }
                }
                src += N;
                drow += CBLK * 4;
            }
            if (t < TKF * 4) {
                int vb = kmax * 64 - t * 16;
                int sz = vb < 0 ? 0 : (vb > 16 ? 16 : vb);
                const float* s = sz ? (inT + (size_t)(k0 + kt) * 16 + t * 4) : inT;
                asm volatile("cp.async.ca.shared.global [%0],[%1],16,%2;"
                             :: "r"(abase + (unsigned)(buf * ATILE * 4 + t * 16)), "l"(s), "r"(sz));
            }
        }
        asm volatile("cp.async.commit_group;" ::: "memory");
    };

    u64 acc[4][8];
#pragma unroll
    for (int i = 0; i < 4; i++)
#pragma unroll
        for (int b = 0; b < 8; b++) acc[i][b] = 0ull;

    prefetch(0, 0);
    prefetch(1, 1);
    for (int ti = 0; ti < ntiles; ti++) {
        asm volatile("cp.async.wait_group 1;" ::: "memory");
        __syncthreads();
        prefetch(ti + 2, (ti + 2) % 3);       // empty commit past end
        int buf = ti % 3;
        const float* sw = wbuf + buf * WTILE;
        const float* sa = abuf + buf * ATILE;
        int kc = min(TKF, kn - ti * TKF);
#pragma unroll
        for (int k = 0; k < TKF; k++) {
            if (k < kc) {
                float4 w4 = *(const float4*)(sw + k * CBLK + 4 * t);
                const ulonglong2* ap = (const ulonglong2*)(sa + k * 16);
                ulonglong2 A0 = ap[0], A1 = ap[1], A2 = ap[2], A3 = ap[3];
                u64 wp_;
                asm("mov.b64 %0,{%1,%1};" : "=l"(wp_) : "f"(w4.x));
                FMA8(acc[0], A0, A1, A2, A3, wp_)
                asm("mov.b64 %0,{%1,%1};" : "=l"(wp_) : "f"(w4.y));
                FMA8(acc[1], A0, A1, A2, A3, wp_)
                asm("mov.b64 %0,{%1,%1};" : "=l"(wp_) : "f"(w4.z));
                FMA8(acc[2], A0, A1, A2, A3, wp_)
                asm("mov.b64 %0,{%1,%1};" : "=l"(wp_) : "f"(w4.w));
                FMA8(acc[3], A0, A1, A2, A3, wp_)
            }
        }
    }
#pragma unroll
    for (int i = 0; i < 4; i++) {
        int n = nblk + 4 * t + i;
        if (n < N) {
            ulonglong2* dst = (ulonglong2*)&g_part[((size_t)blockIdx.y * N + n) * 16];
            dst[0] = make_ulonglong2(acc[i][0], acc[i][1]);
            dst[1] = make_ulonglong2(acc[i][2], acc[i][3]);
            dst[2] = make_ulonglong2(acc[i][4], acc[i][5]);
            dst[3] = make_ulonglong2(acc[i][6], acc[i][7]);
        }
    }
}

// ---------------- split-K reduce + bias ----------------
__global__ void k_fc_reduce(const float* __restrict__ bias, int outsel, int N, int ks,
                            float* __restrict__ dout) {
    int gid = blockIdx.x * 256 + threadIdx.x;
    if (gid >= N * 16) return;
    int n = gid >> 4, b = gid & 15;
    float s = __ldg(bias + n);
#pragma unroll 4
    for (int j = 0; j < ks; j++) s += g_part[((size_t)j * N + n) * 16 + b];
    if (outsel == 3) dout[1648 + b * REC + n] = s;
    else if (outsel == 1) g_h1T[gid] = s;
    else g_h2T[gid] = s;
}

// ---------------- launch ----------------
extern "C" void kernel_launch(void* const* d_in, const int* in_sizes, int n_in,
                              void* d_out, int out_size) {
    const float* x   = (const float*)d_in[0];
    const float* cw  = (const float*)d_in[1];
    const float* cb  = (const float*)d_in[2];
    const float* Wc  = (const float*)d_in[3];
    const float* f1w = (const float*)d_in[4];
    const float* f1b = (const float*)d_in[5];
    const float* f2w = (const float*)d_in[6];
    const float* f2b = (const float*)d_in[7];
    const float* f3w = (const float*)d_in[8];
    const float* f3b = (const float*)d_in[9];
    float* out = (float*)d_out;

    int conv_smem = (C_IN * 81 + CONV_G * C_IN * 9 + CONV_G * 49) * 4;
    int fc_smem = (3 * WTILE + 3 * ATILE) * 4;   // 99840 B
    static int attr_set = 0;
    if (!attr_set) {
        cudaFuncSetAttribute(k_conv_mean, cudaFuncAttributeMaxDynamicSharedMemorySize, conv_smem);
        cudaFuncSetAttribute(k_fc_part, cudaFuncAttributeMaxDynamicSharedMemorySize, fc_smem);
        attr_set = 1;
    }

    k_conv_mean<<<dim3(C_CONV / CONV_G, BATCH), 512, conv_smem>>>(x, cw, cb);
    k_wsum<<<1648, 256>>>(Wc);
    k_route<<<N_OUT, 256>>>(out);
    // fc1: K=1648 N=5562: 6 n-blocks × ks=24 = 144 blocks, chunk 69 (9 tiles)
    k_fc_part<<<dim3(6, 24), 256, fc_smem>>>(0, f1w, K1, H1_DIM, 69);
    k_fc_reduce<<<348, 256>>>(f1b, 1, H1_DIM, 24, out);
    // fc2: K=5562 N=12514: 13 n-blocks × ks=22 = 286 blocks, chunk 253 (32 tiles)
    k_fc_part<<<dim3(13, 22), 256, fc_smem>>>(1, f2w, H1_DIM, H2_DIM, 253);
    k_fc_reduce<<<783, 256>>>(f2b, 2, H2_DIM, 22, out);
    // fc3: K=12514 N=8343: 9 n-blocks × ks=32 = 288 blocks, chunk 392 (49 tiles)
    k_fc_part<<<dim3(9, 32), 256, fc_smem>>>(2, f3w, H2_DIM, REC, 392);
    k_fc_reduce<<<522, 256>>>(f3b, 3, REC, 32, out);
}

// round 12
// speedup vs baseline: 1.2272x; 1.0743x over previous
#include <cuda_runtime.h>
#include <math.h>

#define BATCH 16
#define C_IN 103
#define C_CONV 256
#define N_OUT 103
#define D_OUT 16
#define REC 8343
#define H1_DIM 5562
#define H2_DIM 12514
#define K1 1648
#define CONV_G 8

typedef unsigned long long u64;

// ---------------- static device workspace ----------------
__device__ float g_p[BATCH * C_CONV];
__device__ float g_WsumJ[N_OUT * C_CONV * D_OUT];    // [j][c][o]
__device__ float g_s[N_OUT * BATCH * D_OUT];         // [j][b*16+o]
__device__ float g_f0T[K1 * BATCH];                  // [k][b]
__device__ float g_h1T[H1_DIM * BATCH];
__device__ float g_h2T[H2_DIM * BATCH];
__device__ float g_part[4500000];                    // split-K partials
__device__ unsigned g_barcnt = 0;                    // monotonic ticket barrier

__device__ __forceinline__ unsigned smem_u32(const void* p) {
    return (unsigned)__cvta_generic_to_shared(p);
}

__device__ __forceinline__ void mbwait(unsigned mb, unsigned ph) {
    unsigned done;
    do {
        asm volatile("{\n\t.reg .pred p;\n\t"
                     "mbarrier.try_wait.parity.acquire.cta.shared::cta.b64 p,[%1],%2,0x989680;\n\t"
                     "selp.b32 %0,1,0,p;\n\t}"
                     : "=r"(done) : "r"(mb), "r"(ph) : "memory");
    } while (!done);
}

// ---------------- helpers ----------------
__device__ __forceinline__ float block_reduce_sum(float v, float* sc) {
    int t = threadIdx.x;
#pragma unroll
    for (int o = 16; o > 0; o >>= 1) v += __shfl_xor_sync(0xffffffffu, v, o);
    if ((t & 31) == 0) sc[t >> 5] = v;
    __syncthreads();
    if (t < 32) {
        float w = (t < 8) ? sc[t] : 0.f;
#pragma unroll
        for (int o = 4; o > 0; o >>= 1) w += __shfl_xor_sync(0xffffffffu, w, o);
        if (t == 0) sc[0] = w;
    }
    __syncthreads();
    float r = sc[0];
    __syncthreads();
    return r;
}

__device__ __forceinline__ float block_reduce_max(float v, float* sc) {
    int t = threadIdx.x;
#pragma unroll
    for (int o = 16; o > 0; o >>= 1) v = fmaxf(v, __shfl_xor_sync(0xffffffffu, v, o));
    if ((t & 31) == 0) sc[t >> 5] = v;
    __syncthreads();
    if (t < 32) {
        float w = (t < 8) ? sc[t] : -1e30f;
#pragma unroll
        for (int o = 4; o > 0; o >>= 1) w = fmaxf(w, __shfl_xor_sync(0xffffffffu, w, o));
        if (t == 0) sc[0] = w;
    }
    __syncthreads();
    float r = sc[0];
    __syncthreads();
    return r;
}

// monotonic-ticket global barrier: no reset, survives graph replays
__device__ __forceinline__ void gbar(unsigned nb) {
    __syncthreads();
    if (threadIdx.x == 0) {
        __threadfence();
        unsigned ticket = atomicAdd(&g_barcnt, 1u);
        unsigned target = (ticket / nb + 1u) * nb;
        while (*(volatile unsigned*)&g_barcnt < target) { __nanosleep(64); }
        __threadfence();
    }
    __syncthreads();
}

// ---------------- conv 3x3 VALID + relu + spatial mean -> p[b][oc] ----------------
__global__ void k_conv_mean(const float* __restrict__ x, const float* __restrict__ w,
                            const float* __restrict__ bias) {
    extern __shared__ float smem[];
    float* sx = smem;
    float* sw = sx + C_IN * 81;
    float* sacc = sw + CONV_G * C_IN * 9;
    int b = blockIdx.y;
    int oc0 = blockIdx.x * CONV_G;
    int t = threadIdx.x;
    for (int i = t; i < C_IN * 81; i += blockDim.x) sx[i] = x[b * C_IN * 81 + i];
    for (int i = t; i < CONV_G * C_IN * 9; i += blockDim.x) sw[i] = w[oc0 * C_IN * 9 + i];
    __syncthreads();
    if (t < CONV_G * 49) {
        int ocl = t / 49, pos = t % 49, oy = pos / 7, ox = pos % 7;
        float acc = bias[oc0 + ocl];
        const float* wp = &sw[ocl * C_IN * 9];
        for (int ic = 0; ic < C_IN; ic++) {
            const float* xp = &sx[ic * 81 + oy * 9 + ox];
            const float* wq = &wp[ic * 9];
#pragma unroll
            for (int ky = 0; ky < 3; ky++)
#pragma unroll
                for (int kx = 0; kx < 3; kx++)
                    acc = fmaf(xp[ky * 9 + kx], wq[ky * 3 + kx], acc);
        }
        sacc[t] = fmaxf(acc, 0.f);
    }
    __syncthreads();
    if (t < CONV_G) {
        float s = 0.f;
#pragma unroll
        for (int i = 0; i < 49; i++) s += sacc[t * 49 + i];
        g_p[b * C_CONV + oc0 + t] = s * (1.f / 49.f);
    }
}

// ---------------- WsumJ[j][c][o] = sum_i W_caps[c][j][o][i] ----------------
__global__ void k_wsum(const float* __restrict__ Wc) {
    int e = blockIdx.x * 256 + threadIdx.x;   // 421888 = C_CONV*N_OUT*16
    const float4* p = (const float4*)(Wc + (size_t)e * 32);
    float s = 0.f;
#pragma unroll
    for (int i = 0; i < 8; i++) {
        float4 v = __ldg(p + i);
        s += (v.x + v.y) + (v.z + v.w);
    }
    int c = e / 1648;
    int r = e - c * 1648;
    int j = r >> 4, o = r & 15;
    g_WsumJ[((j << 8) + c) * 16 + o] = s;
}

// ---------------- single persistent routing kernel (3 iters) + epilogue ----------------
__global__ void k_route(float* __restrict__ dout) {
    __shared__ float shw[C_CONV * 17];
    __shared__ float shq[C_CONV * 17];
    __shared__ float shcq[C_CONV * 17];
    __shared__ float shc[C_CONV];
    __shared__ float shv[256];
    __shared__ float shba[16];
    __shared__ float sc[8];
    int j = blockIdx.x, t = threadIdx.x;

    for (int b = 0; b < BATCH; b++) {
        float v = g_p[b * 256 + t];
        float msq = block_reduce_sum(v * v, sc);
        shq[t * 17 + b] = v * sqrtf(msq) / (1.f + msq);
    }
    const float4* wj = (const float4*)(g_WsumJ + (size_t)j * 4096);
#pragma unroll
    for (int r = 0; r < 4; r++) {
        int i4 = r * 256 + t;
        float4 v = wj[i4];
        int c = i4 >> 2, o = (i4 & 3) * 4;
        shw[c * 17 + o] = v.x; shw[c * 17 + o + 1] = v.y;
        shw[c * 17 + o + 2] = v.z; shw[c * 17 + o + 3] = v.w;
    }
    float bv = 1.f;
    __syncthreads();

    int bb = t >> 4, oo = t & 15;
    for (int it = 0; it < 3; it++) {
        float m = block_reduce_max(bv, sc);
        float e = expf(bv - m);
        float ssum = block_reduce_sum(e, sc);
        shc[t] = e / ssum;
        __syncthreads();
        for (int i = t; i < 4096; i += 256) {
            int c = i >> 4, b = i & 15;
            shcq[c * 17 + b] = shc[c] * shq[c * 17 + b];
        }
        __syncthreads();
        float acc = 0.f;
#pragma unroll 8
        for (int c = 0; c < 256; c++) acc = fmaf(shcq[c * 17 + bb], shw[c * 17 + oo], acc);
        __stcg(&g_s[j * 256 + t], acc);
        gbar(N_OUT);
        float msq = 0.f;
#pragma unroll 4
        for (int jj = 0; jj < N_OUT; jj++) {
            float sv = __ldcg(&g_s[jj * 256 + t]);
            msq = fmaf(sv, sv, msq);
        }
        float vv = acc * sqrtf(msq) / (1.f + msq);
        shv[t] = vv;
        __syncthreads();
        if (it < 2) {
            float g = 0.f;
#pragma unroll
            for (int b2 = 0; b2 < BATCH; b2++) {
                float d = 0.f;
#pragma unroll
                for (int o2 = 0; o2 < 16; o2++) d = fmaf(shw[t * 17 + o2], shv[b2 * 16 + o2], d);
                g = fmaf(shq[t * 17 + b2], d, g);
            }
            bv += g * (1.f / 16.f);
            gbar(N_OUT);
        }
    }
    if (t < 16) {
        float r = 0.f;
#pragma unroll
        for (int o2 = 0; o2 < 16; o2++) { float q = shv[t * 16 + o2]; r = fmaf(q, q, r); }
        float ba = sqrtf(r);
        shba[t] = ba;
        dout[t * N_OUT + j] = ba;
    }
    __syncthreads();
    g_f0T[(j * 16 + oo) * 16 + bb] = shv[t] * shba[bb];
}

// ---------------- skinny GEMM (M=16): bulk-copy (UBLKCP) pipeline ----------------
#define FMA8(ACC, A0, A1, A2, A3, WP)                                               \
    asm("fma.rn.f32x2 %0,%1,%2,%0;" : "+l"(ACC[0]) : "l"(A0.x), "l"(WP));           \
    asm("fma.rn.f32x2 %0,%1,%2,%0;" : "+l"(ACC[1]) : "l"(A0.y), "l"(WP));           \
    asm("fma.rn.f32x2 %0,%1,%2,%0;" : "+l"(ACC[2]) : "l"(A1.x), "l"(WP));           \
    asm("fma.rn.f32x2 %0,%1,%2,%0;" : "+l"(ACC[3]) : "l"(A1.y), "l"(WP));           \
    asm("fma.rn.f32x2 %0,%1,%2,%0;" : "+l"(ACC[4]) : "l"(A2.x), "l"(WP));           \
    asm("fma.rn.f32x2 %0,%1,%2,%0;" : "+l"(ACC[5]) : "l"(A2.y), "l"(WP));           \
    asm("fma.rn.f32x2 %0,%1,%2,%0;" : "+l"(ACC[6]) : "l"(A3.x), "l"(WP));           \
    asm("fma.rn.f32x2 %0,%1,%2,%0;" : "+l"(ACC[7]) : "l"(A3.y), "l"(WP));

#define TKF 8
#define CBLK 1024
#define SROWF 1040                       // floats per smem row (4160 B, 16B aligned, holds 4112+shift)
#define WTILEF (TKF * SROWF)             // 8320 floats per W tile
#define WTILEB (WTILEF * 4)              // 33280 B
#define ATILEB 512                       // 8 rows * 64 B

__global__ __launch_bounds__(256, 2) void k_fc_part(int insel, const float* __restrict__ W,
                                                    int K, int N, int kchunk) {
    extern __shared__ float smem[];
    const float* inT = (insel == 0) ? g_f0T : (insel == 1) ? g_h1T : g_h2T;
    int t = threadIdx.x;
    int k0 = blockIdx.y * kchunk;
    int kn = min(K - k0, kchunk);
    int nblk = blockIdx.x * CBLK;
    int nb = min(CBLK, N - nblk);
    unsigned sbase = smem_u32(smem);
    unsigned wdst = sbase;
    unsigned adst = sbase + 3 * WTILEB;
    unsigned mbb = sbase + 3 * WTILEB + 3 * ATILEB;
    u64 wendB = (u64)W + (size_t)K * N * 4ull;
    unsigned nbB = (unsigned)nb * 4u;
    int ntiles = (kn + TKF - 1) / TKF;

    if (t == 0) {
#pragma unroll
        for (int s = 0; s < 3; s++)
            asm volatile("mbarrier.init.shared.b64 [%0],1;" :: "r"(mbb + s * 8) : "memory");
        asm volatile("fence.proxy.async.shared::cta;" ::: "memory");
    }
    __syncthreads();

    // last-row clip precompute (only the final row of W can over-read)
    bool needclip = false;
    int covered = 0x7fffffff;
    if (k0 + kn == K) {
        u64 srcp = (u64)W + ((size_t)(K - 1) * N + nblk) * 4ull;
        u64 al = srcp & ~(u64)15;
        unsigned off = (unsigned)(srcp & 15);
        unsigned szf = (off + nbB + 15u) & ~15u;
        if (al + szf > wendB) {
            needclip = true;
            covered = (int)((((wendB - al) & ~(u64)15) - off) >> 2);
        }
    }

    auto issue = [&](int ti, int slot) {
        int kt = ti * TKF;
        if (kt >= kn) return;
        int kmax = min(TKF, kn - kt);
        unsigned mb = mbb + slot * 8;
        // pass 1: total tx bytes
        unsigned tx = (unsigned)kmax * 64u;
        {
            u64 srcp = (u64)W + ((size_t)(k0 + kt) * N + nblk) * 4ull;
#pragma unroll
            for (int k = 0; k < TKF; k++) {
                if (k < kmax) {
                    u64 al = srcp & ~(u64)15;
                    unsigned off = (unsigned)(srcp & 15);
                    unsigned sz = (off + nbB + 15u) & ~15u;
                    if (al + sz > wendB) sz = (unsigned)((wendB - al) & ~(u64)15);
                    tx += sz;
                }
                srcp += (u64)N * 4ull;
            }
        }
        asm volatile("mbarrier.arrive.expect_tx.shared.b64 _,[%0],%1;" :: "r"(mb), "r"(tx) : "memory");
        // pass 2: issue bulk copies
        {
            u64 srcp = (u64)W + ((size_t)(k0 + kt) * N + nblk) * 4ull;
            unsigned drow = wdst + (unsigned)slot * WTILEB;
#pragma unroll
            for (int k = 0; k < TKF; k++) {
                if (k < kmax) {
                    u64 al = srcp & ~(u64)15;
                    unsigned off = (unsigned)(srcp & 15);
                    unsigned sz = (off + nbB + 15u) & ~15u;
                    if (al + sz > wendB) sz = (unsigned)((wendB - al) & ~(u64)15);
                    asm volatile("cp.async.bulk.shared::cta.global.mbarrier::complete_tx::bytes [%0],[%1],%2,[%3];"
                                 :: "r"(drow), "l"(al), "r"(sz), "r"(mb) : "memory");
                }
                srcp += (u64)N * 4ull;
                drow += SROWF * 4u;
            }
            asm volatile("cp.async.bulk.shared::cta.global.mbarrier::complete_tx::bytes [%0],[%1],%2,[%3];"
                         :: "r"(adst + (unsigned)slot * ATILEB),
                    "l"((u64)inT + (size_t)(k0 + kt) * 64ull),
                    "r"((unsigned)kmax * 64u), "r"(mb) : "memory");
        }
    };

    if (t == 0) { issue(0, 0); issue(1, 1); }

    u64 acc[4][8];
#pragma unroll
    for (int i = 0; i < 4; i++)
#pragma unroll
        for (int b = 0; b < 8; b++) acc[i][b] = 0ull;

    u64 wq4 = ((u64)W) >> 2;    // element-granular base (W is 16B aligned)

    for (int ti = 0; ti < ntiles; ti++) {
        int slot = ti % 3;
        unsigned parity = (unsigned)((ti / 3) & 1);
        mbwait(mbb + slot * 8, parity);
        __syncthreads();
        if (t == 0) issue(ti + 2, (ti + 2) % 3);
        const float* sw = smem + slot * WTILEF;
        const float* sa = smem + 3 * WTILEF + slot * 128;
        int kc = min(TKF, kn - ti * TKF);
#pragma unroll
        for (int k = 0; k < TKF; k++) {
            if (k < kc) {
                int kg = k0 + ti * TKF + k;
                unsigned off4 = (unsigned)((wq4 + (size_t)kg * N + (size_t)nblk) & 3);
                const float* srow = sw + k * SROWF + off4;
                float w0 = srow[t], w1 = srow[t + 256], w2 = srow[t + 512], w3 = srow[t + 768];
                if (needclip && kg == K - 1) {
                    const float* wl = W + (size_t)(K - 1) * N;
                    if (t >= covered)       w0 = (nblk + t < N)       ? __ldg(wl + nblk + t)       : 0.f;
                    if (t + 256 >= covered) w1 = (nblk + t + 256 < N) ? __ldg(wl + nblk + t + 256) : 0.f;
                    if (t + 512 >= covered) w2 = (nblk + t + 512 < N) ? __ldg(wl + nblk + t + 512) : 0.f;
                    if (t + 768 >= covered) w3 = (nblk + t + 768 < N) ? __ldg(wl + nblk + t + 768) : 0.f;
                }
                const ulonglong2* ap = (const ulonglong2*)(sa + k * 16);
                ulonglong2 A0 = ap[0], A1 = ap[1], A2 = ap[2], A3 = ap[3];
                u64 wp_;
                asm("mov.b64 %0,{%1,%1};" : "=l"(wp_) : "f"(w0));
                FMA8(acc[0], A0, A1, A2, A3, wp_)
                asm("mov.b64 %0,{%1,%1};" : "=l"(wp_) : "f"(w1));
                FMA8(acc[1], A0, A1, A2, A3, wp_)
                asm("mov.b64 %0,{%1,%1};" : "=l"(wp_) : "f"(w2));
                FMA8(acc[2], A0, A1, A2, A3, wp_)
                asm("mov.b64 %0,{%1,%1};" : "=l"(wp_) : "f"(w3));
                FMA8(acc[3], A0, A1, A2, A3, wp_)
            }
        }
    }
#pragma unroll
    for (int i = 0; i < 4; i++) {
        int n = nblk + t + 256 * i;
        if (n < N) {
            ulonglong2* dst = (ulonglong2*)&g_part[((size_t)blockIdx.y * N + n) * 16];
            dst[0] = make_ulonglong2(acc[i][0], acc[i][1]);
            dst[1] = make_ulonglong2(acc[i][2], acc[i][3]);
            dst[2] = make_ulonglong2(acc[i][4], acc[i][5]);
            dst[3] = make_ulonglong2(acc[i][6], acc[i][7]);
        }
    }
}

// ---------------- split-K reduce + bias ----------------
__global__ void k_fc_reduce(const float* __restrict__ bias, int outsel, int N, int ks,
                            float* __restrict__ dout) {
    int gid = blockIdx.x * 256 + threadIdx.x;
    if (gid >= N * 16) return;
    int n = gid >> 4, b = gid & 15;
    float s = __ldg(bias + n);
#pragma unroll 4
    for (int j = 0; j < ks; j++) s += g_part[((size_t)j * N + n) * 16 + b];
    if (outsel == 3) dout[1648 + b * REC + n] = s;
    else if (outsel == 1) g_h1T[gid] = s;
    else g_h2T[gid] = s;
}

// ---------------- launch ----------------
extern "C" void kernel_launch(void* const* d_in, const int* in_sizes, int n_in,
                              void* d_out, int out_size) {
    const float* x   = (const float*)d_in[0];
    const float* cw  = (const float*)d_in[1];
    const float* cb  = (const float*)d_in[2];
    const float* Wc  = (const float*)d_in[3];
    const float* f1w = (const float*)d_in[4];
    const float* f1b = (const float*)d_in[5];
    const float* f2w = (const float*)d_in[6];
    const float* f2b = (const float*)d_in[7];
    const float* f3w = (const float*)d_in[8];
    const float* f3b = (const float*)d_in[9];
    float* out = (float*)d_out;

    int conv_smem = (C_IN * 81 + CONV_G * C_IN * 9 + CONV_G * 49) * 4;
    int fc_smem = 3 * WTILEB + 3 * ATILEB + 32;   // 101,408 B
    static int attr_set = 0;
    if (!attr_set) {
        cudaFuncSetAttribute(k_conv_mean, cudaFuncAttributeMaxDynamicSharedMemorySize, conv_smem);
        cudaFuncSetAttribute(k_fc_part, cudaFuncAttributeMaxDynamicSharedMemorySize, fc_smem);
        attr_set = 1;
    }

    k_conv_mean<<<dim3(C_CONV / CONV_G, BATCH), 512, conv_smem>>>(x, cw, cb);
    k_wsum<<<1648, 256>>>(Wc);
    k_route<<<N_OUT, 256>>>(out);
    // fc1: K=1648 N=5562: 6 n-blocks × ks=49 = 294 blocks, chunk 34
    k_fc_part<<<dim3(6, 49), 256, fc_smem>>>(0, f1w, K1, H1_DIM, 34);
    k_fc_reduce<<<348, 256>>>(f1b, 1, H1_DIM, 49, out);
    // fc2: K=5562 N=12514: 13 n-blocks × ks=22 = 286 blocks, chunk 253
    k_fc_part<<<dim3(13, 22), 256, fc_smem>>>(1, f2w, H1_DIM, H2_DIM, 253);
    k_fc_reduce<<<783, 256>>>(f2b, 2, H2_DIM, 22, out);
    // fc3: K=12514 N=8343: 9 n-blocks × ks=32 = 288 blocks, chunk 392
    k_fc_part<<<dim3(9, 32), 256, fc_smem>>>(2, f3w, H2_DIM, REC, 392);
    k_fc_reduce<<<522, 256>>>(f3b, 3, REC, 32, out);
}